// round 17
// baseline (speedup 1.0000x reference)
#include <cuda_runtime.h>

#define D    512
#define DD   (D * D)
#define PD4  (DD / 4)     // float4 per channel
#define C1   128
#define C2   64
#define KPAD 16           // u64 stride per argmax key -> 128B across LTS slices

// ---------------- device scratch (no allocations allowed) ----------------
// Packed argmax keys: (monotonic(value) << 32) | (511 - o); atomicMax idempotent.
__device__ unsigned long long g_key1[D * KPAD];
__device__ unsigned long long g_key2[D * KPAD];
__device__ __align__(16) float g_p1[2][DD];   // W1 c-split partial sums
__device__ __align__(16) float g_p2[2][DD];   // W2 c-split partial sums
__device__ __align__(16) float g_diff1[C1 * D];
__device__ __align__(16) float g_diff2[C2 * D];
__device__ float g_h1[C2 * D];
__device__ unsigned g_cnt_c1, g_cnt_s1, g_cnt_c2, g_cnt_s2;  // reset in K1

__device__ __forceinline__ float4 f4add(float4 a, float4 b) {
    a.x += b.x; a.y += b.y; a.z += b.z; a.w += b.w; return a;
}
__device__ __forceinline__ unsigned mono(float f) {
    unsigned b = __float_as_uint(f);
    return (b & 0x80000000u) ? ~b : (b | 0x80000000u);
}
__device__ __forceinline__ int decode_node(unsigned long long k) {
    return 511 - (int)(unsigned)(k & 0xffffffffu);
}
__device__ __forceinline__ void amax4(unsigned long long* key, float4 acc, int o, int j) {
    const unsigned long long lo = (unsigned long long)(511 - o);
    const int i = j * 4;
    atomicMax(&key[(i + 0) * KPAD], ((unsigned long long)mono(acc.x) << 32) | lo);
    atomicMax(&key[(i + 1) * KPAD], ((unsigned long long)mono(acc.y) << 32) | lo);
    atomicMax(&key[(i + 2) * KPAD], ((unsigned long long)mono(acc.z) << 32) | lo);
    atomicMax(&key[(i + 3) * KPAD], ((unsigned long long)mono(acc.w) << 32) | lo);
}
__device__ __forceinline__ void spin_until(volatile unsigned* p, unsigned v) {
    while (*p != v) __nanosleep(64);
}

// Row-group partial sum: block owns 4 consecutive o-rows (8KB contiguous per
// channel visit -> DRAM row locality) for NCH channels starting at ch0.
// Tile = 4 rows x 512 i = 512 float4 slots; thread t owns slots t and t+256.
template <int NCH>
__device__ __forceinline__ void partial_rows(const float* __restrict__ W, int g, int ch0,
                                             float* __restrict__ dst, int t) {
    const float4* Wp = reinterpret_cast<const float4*>(W) + (size_t)ch0 * PD4 + g * 512;
    float4 a0 = make_float4(0.f, 0.f, 0.f, 0.f), a1 = a0;
#pragma unroll
    for (int ch = 0; ch < NCH; ch += 4) {
        float4 v0[4], v1[4];
#pragma unroll
        for (int k = 0; k < 4; ++k) {
            const float4* p = Wp + (size_t)(ch + k) * PD4;
            v0[k] = __ldcs(p + t);
            v1[k] = __ldcs(p + t + 256);
        }
#pragma unroll
        for (int k = 0; k < 4; ++k) { a0 = f4add(a0, v0[k]); a1 = f4add(a1, v1[k]); }
    }
    float4* d4 = reinterpret_cast<float4*>(dst) + g * 512;
    __stcg(d4 + t, a0);
    __stcg(d4 + t + 256, a1);
}

// Combine two partials for group g, fixed order, fused argmax into key.
__device__ __forceinline__ void combine_group(const float* __restrict__ p0,
                                              const float* __restrict__ p1,
                                              unsigned long long* __restrict__ key,
                                              int g, int t) {
    const float4* a = reinterpret_cast<const float4*>(p0) + g * 512;
    const float4* b = reinterpret_cast<const float4*>(p1) + g * 512;
    float4 s0 = f4add(__ldcg(a + t),       __ldcg(b + t));
    float4 s1 = f4add(__ldcg(a + t + 256), __ldcg(b + t + 256));
    amax4(key, s0, g * 4 + (t >> 7),           t & 127);   // slot t
    amax4(key, s1, g * 4 + ((t + 256) >> 7),   t & 127);   // slot t+256
}

// ====== K1: W1 partial sums (row-grouped) + zero diffs + reset flags ========
// 256 blocks x 256 threads: block b -> group g=b>>1 (rows 4g..4g+3), cs=b&1
// (channels cs*64..cs*64+63). All 256 blocks co-resident -> DRAM self-balances.
__global__ void __launch_bounds__(256) k1_w1_partials(const float* __restrict__ W1) {
    const int b = blockIdx.x;
    const int t = threadIdx.x;

    if (b == 0 && t == 0) { g_cnt_c1 = 0u; g_cnt_s1 = 0u; g_cnt_c2 = 0u; g_cnt_s2 = 0u; }
    if (t < 96) {                           // 256*96 f4 = 98304 floats = diffs exactly
        const int idx = b * 96 + t;
        const float4 z = make_float4(0.f, 0.f, 0.f, 0.f);
        if (idx < C1 * D / 4) reinterpret_cast<float4*>(g_diff1)[idx] = z;
        else                  reinterpret_cast<float4*>(g_diff2)[idx - C1 * D / 4] = z;
    }

    partial_rows<64>(W1, b >> 1, (b & 1) * 64, g_p1[b & 1], t);
}

// ====== K2: W2 partials || combine1 -> scatter1 -> gemm1 (flag-chained) =====
// 768 blocks x 256 threads. Waits only target strictly-lower bid groups.
//   [0,256):   W2 partials, g=b>>1, cs=b&1 (32 ch each)         (no wait)
//   [256,384): combine1 -> key1 (p1 ready: kernel boundary); count c1
//   [384,640): scatter1 -> diff1 (waits c1==128); count s1
//   [640,768): gemm1 -> g_h1 (waits s1==256)
__global__ void __launch_bounds__(256) k2_w2_and_tail1(
    const float* __restrict__ W2, const float* __restrict__ x,
    const float* __restrict__ W1, const float* __restrict__ Wc1,
    const float* __restrict__ bc1)
{
    const int b = blockIdx.x;
    const int t = threadIdx.x;
    __shared__ float sw[C1];

    if (b < 256) {
        partial_rows<32>(W2, b >> 1, (b & 1) * 32, g_p2[b & 1], t);
    } else if (b < 384) {
        combine_group(g_p1[0], g_p1[1], g_key1, b - 256, t);
        __syncthreads();
        if (t == 0) { __threadfence(); atomicAdd(&g_cnt_c1, 1u); }
    } else if (b < 640) {
        // scatter1: one (c,i) pair per thread (65536 total)
        const int sb = b - 384;
        const int c  = sb >> 1;
        const int i  = (sb & 1) * 256 + t;
        if (t == 0) spin_until(&g_cnt_c1, 128u);
        __syncthreads();
        const int n  = decode_node(__ldcg(&g_key1[i * KPAD]));
        const float xv = fmaxf(x[c * D + i], 0.f);
        const float w  = __ldg(&W1[(size_t)c * DD + (size_t)n * D + i]);
        atomicAdd(&g_diff1[c * D + n], w * xv);      // spread L2 atomics
        __syncthreads();
        if (t == 0) { __threadfence(); atomicAdd(&g_cnt_s1, 1u); }
    } else {
        // gemm1 -> relu -> g_h1: one output per thread (32768 total)
        const int gb = b - 640;
        const int o  = gb >> 1;
        const int d  = (gb & 1) * 256 + t;
        if (t < C1) sw[t] = Wc1[o * C1 + t];
        if (t == 0) spin_until(&g_cnt_s1, 256u);
        __syncthreads();

        float acc = bc1[o];
        float v[8];
#pragma unroll
        for (int ch = 0; ch < C1; ch += 8) {
#pragma unroll
            for (int k = 0; k < 8; ++k) v[k] = __ldcg(&g_diff1[(ch + k) * D + d]);
#pragma unroll
            for (int k = 0; k < 8; ++k) acc += sw[ch + k] * v[k];
        }
        g_h1[o * D + d] = fmaxf(acc, 0.f);
    }
}

// ====== K3: combine2 -> scatter2 -> gemm2 + residual (flag-chained) =========
// 512 blocks x 256 threads.
//   [0,128):   combine2 -> key2 (p2 ready: kernel boundary); count c2
//   [128,256): scatter2 -> diff2 (waits c2==128); count s2
//   [256,512): gemm2 + residual -> out (waits s2==128)
__global__ void __launch_bounds__(256) k3_tail2(
    const float* __restrict__ W2, const float* __restrict__ Wc2,
    const float* __restrict__ bc2, const float* __restrict__ x,
    float* __restrict__ out)
{
    const int b = blockIdx.x;
    const int t = threadIdx.x;
    __shared__ float sw[C2];

    if (b < 128) {
        combine_group(g_p2[0], g_p2[1], g_key2, b, t);
        __syncthreads();
        if (t == 0) { __threadfence(); atomicAdd(&g_cnt_c2, 1u); }
    } else if (b < 256) {
        // scatter2: one (o,d) per thread (32768 total); h1 ready (kernel boundary)
        const int sb = b - 128;
        const int o  = sb >> 1;
        const int d  = (sb & 1) * 256 + t;
        if (t == 0) spin_until(&g_cnt_c2, 128u);
        __syncthreads();
        const int n  = decode_node(__ldcg(&g_key2[d * KPAD]));
        const float w = __ldg(&W2[(size_t)o * DD + (size_t)n * D + d]);
        const float h = __ldcg(&g_h1[o * D + d]);    // already relu'd
        atomicAdd(&g_diff2[o * D + n], w * h);
        __syncthreads();
        if (t == 0) { __threadfence(); atomicAdd(&g_cnt_s2, 1u); }
    } else {
        // gemm2 + residual: one output per thread (65536 total)
        const int gb = b - 256;
        const int o  = gb >> 1;
        const int d  = (gb & 1) * 256 + t;
        if (t < C2) sw[t] = Wc2[o * C2 + t];
        const float xr = fmaxf(x[o * D + d], 0.f);
        if (t == 0) spin_until(&g_cnt_s2, 128u);
        __syncthreads();

        float acc = bc2[o];
        float v[8];
#pragma unroll
        for (int ch = 0; ch < C2; ch += 8) {
#pragma unroll
            for (int k = 0; k < 8; ++k) v[k] = __ldcg(&g_diff2[(ch + k) * D + d]);
#pragma unroll
            for (int k = 0; k < 8; ++k) acc += sw[ch + k] * v[k];
        }
        out[o * D + d] = xr + acc;
    }
}

// ---------------- launch -----------------------------------------------------
extern "C" void kernel_launch(void* const* d_in, const int* in_sizes, int n_in,
                              void* d_out, int out_size) {
    const float* x   = (const float*)d_in[0];
    const float* W1  = (const float*)d_in[1];
    const float* Wc1 = (const float*)d_in[2];
    const float* bc1 = (const float*)d_in[3];
    const float* W2  = (const float*)d_in[4];
    const float* Wc2 = (const float*)d_in[5];
    const float* bc2 = (const float*)d_in[6];
    float* out = (float*)d_out;

    k1_w1_partials<<<256, 256>>>(W1);                      // 8KB-chunk W1 stream
    k2_w2_and_tail1<<<768, 256>>>(W2, x, W1, Wc1, bc1);    // W2 stream || tail-1
    k3_tail2<<<512, 256>>>(W2, Wc2, bc2, x, out);          // combine2 + tail-2
}